// round 8
// baseline (speedup 1.0000x reference)
#include <cuda_runtime.h>
#include <cuda_bf16.h>
#include <math.h>
#include <stdint.h>

// Problem constants
#define B_  4
#define N_  4096
#define U_  512
#define M1  (B_ * N_)
#define QKVLD 1536

// GEMM tiling: CTA 128x128, 4 warps (2x2), warp tile 64x64, BK=64, 2 CTA/SM
#define BM 128
#define BN 128
#define BK 64
#define SKB 144          // smem row stride bytes (64*2 + 16 pad)

static constexpr int ATILE = BM * SKB;          // 18432 B
static constexpr int SM_A0 = 0;
static constexpr int SM_B0 = 2 * ATILE;
static constexpr int SM_TOTAL = 4 * ATILE;      // 73728 B

// ---------------- scratch (device globals; no allocation allowed) ----------
__device__ __align__(16) __nv_bfloat16 g_xb  [(size_t)M1 * U_];
__device__ __align__(16) __nv_bfloat16 g_QKV [(size_t)M1 * QKVLD];    // Q|K|V per row
__device__ __align__(16) __nv_bfloat16 g_VT  [(size_t)M1 * U_];       // per batch [U, N]
__device__ __align__(16) __nv_bfloat16 g_S   [(size_t)B_ * N_ * N_];  // 128 MB
__device__ __align__(16) __nv_bfloat16 g_C   [(size_t)M1 * U_];       // ctx
__device__ __align__(16) __nv_bfloat16 g_WQKVT[(size_t)3 * U_ * U_];  // [1536,512]
__device__ __align__(16) __nv_bfloat16 g_WPT [(size_t)U_ * U_];
__device__ __align__(16) float         g_bqkv[QKVLD];

// ---------------- PTX helpers ----------------------------------------------
__device__ __forceinline__ uint32_t smem_u32(const void* p) {
    uint32_t a;
    asm("{ .reg .u64 t; cvta.to.shared.u64 t, %1; cvt.u32.u64 %0, t; }" : "=r"(a) : "l"(p));
    return a;
}
#define CP_ASYNC16(dst, src) \
    asm volatile("cp.async.cg.shared.global [%0], [%1], 16;\n" :: "r"(dst), "l"(src))
#define CP_COMMIT() asm volatile("cp.async.commit_group;\n" ::: "memory")
#define CP_WAIT(n)  asm volatile("cp.async.wait_group %0;\n" :: "n"(n) : "memory")

__device__ __forceinline__ void ldsm_x4(uint32_t& r0, uint32_t& r1, uint32_t& r2,
                                        uint32_t& r3, uint32_t addr) {
    asm volatile("ldmatrix.sync.aligned.m8n8.x4.shared.b16 {%0,%1,%2,%3}, [%4];"
                 : "=r"(r0), "=r"(r1), "=r"(r2), "=r"(r3) : "r"(addr));
}
__device__ __forceinline__ void mma_bf16(float c[4],
                                         uint32_t a0, uint32_t a1, uint32_t a2, uint32_t a3,
                                         uint32_t b0, uint32_t b1) {
    asm volatile(
        "mma.sync.aligned.m16n8k16.row.col.f32.bf16.bf16.f32 "
        "{%0,%1,%2,%3}, {%4,%5,%6,%7}, {%8,%9}, {%0,%1,%2,%3};\n"
        : "+f"(c[0]), "+f"(c[1]), "+f"(c[2]), "+f"(c[3])
        : "r"(a0), "r"(a1), "r"(a2), "r"(a3), "r"(b0), "r"(b1));
}

// ---------------------------------------------------------------------------
// bf16 NT GEMM:  C[z] = scale * A[z] @ B[z]^T (+bias) (+residual)
// A: [M,K] lda-strided. B: [N,K] ldb-strided. M,N % 128 == 0, K % 64 == 0.
// 128 threads, 4 warps in 2x2, warp tile 64x64.
// ---------------------------------------------------------------------------
template <bool OBF16>
__global__ __launch_bounds__(128, 2)
void gemm_bf16(const __nv_bfloat16* __restrict__ A,
               const __nv_bfloat16* __restrict__ Bm,
               const float* __restrict__ bias,
               const float* __restrict__ residual,
               void* __restrict__ Cout,
               int N, int K, int lda, int ldb, int ldc,
               long long sA, long long sB, long long sC,
               float scale)
{
    extern __shared__ char smem[];
    const uint32_t sbase = smem_u32(smem);
    const int tid  = threadIdx.x;
    const int wid  = tid >> 5;
    const int lane = tid & 31;

    const int z = blockIdx.z;
    A  += (long long)z * sA;
    Bm += (long long)z * sB;

    const int rowBase = blockIdx.y * BM;
    const int colBase = blockIdx.x * BN;
    const int warpM = (wid & 1) * 64;
    const int warpN = (wid >> 1) * 64;

    const __nv_bfloat16* Aptr = A + (long long)rowBase * lda;
    const __nv_bfloat16* Bptr = Bm + (long long)colBase * ldb;

    float acc[4][8][4];
    #pragma unroll
    for (int mi = 0; mi < 4; mi++)
        #pragma unroll
        for (int ni = 0; ni < 8; ni++)
            #pragma unroll
            for (int r = 0; r < 4; r++)
                acc[mi][ni][r] = 0.0f;

    // loaders: 128 threads, A 1024 chunks (8/thread), B 1024 chunks (8/thread)
    const int lr = tid >> 3;            // 0..15
    const int lc = tid & 7;             // 16B chunk 0..7
    auto load_tile = [&](int s, int k0) {
        const uint32_t abase = sbase + SM_A0 + s * ATILE;
        const uint32_t bbase = sbase + SM_B0 + s * ATILE;
        #pragma unroll
        for (int i = 0; i < 8; i++) {
            const int r = lr + i * 16;
            CP_ASYNC16(abase + r * SKB + lc * 16,
                       Aptr + (long long)r * lda + k0 + lc * 8);
        }
        #pragma unroll
        for (int i = 0; i < 8; i++) {
            const int r = lr + i * 16;
            CP_ASYNC16(bbase + r * SKB + lc * 16,
                       Bptr + (long long)r * ldb + k0 + lc * 8);
        }
        CP_COMMIT();
    };

    const int lm = lane & 7;
    const int lt = lane >> 3;
    const int aRowOff = lm + (lt & 1) * 8;
    const int aKOff   = (lt >> 1) * 8;
    const int bRowOff = lm + (lt >> 1) * 8;
    const int bKOff   = (lt & 1) * 8;

    const int T = K / BK;
    load_tile(0, 0);

    for (int t = 0; t < T; t++) {
        const int s = t & 1;
        if (t + 1 < T) {
            load_tile((t + 1) & 1, (t + 1) * BK);
            CP_WAIT(1);
        } else {
            CP_WAIT(0);
        }
        __syncthreads();

        const uint32_t Asb = sbase + SM_A0 + s * ATILE;
        const uint32_t Bsb = sbase + SM_B0 + s * ATILE;

        #pragma unroll
        for (int kk = 0; kk < 4; kk++) {
            uint32_t a[4][4], b[8][2];
            #pragma unroll
            for (int mi = 0; mi < 4; mi++) {
                uint32_t addr = Asb + (warpM + mi * 16 + aRowOff) * SKB
                              + (kk * 16 + aKOff) * 2;
                ldsm_x4(a[mi][0], a[mi][1], a[mi][2], a[mi][3], addr);
            }
            #pragma unroll
            for (int p = 0; p < 4; p++) {
                uint32_t addr = Bsb + (warpN + p * 16 + bRowOff) * SKB
                              + (kk * 16 + bKOff) * 2;
                uint32_t r0, r1, r2, r3;
                ldsm_x4(r0, r1, r2, r3, addr);
                b[2*p][0] = r0;   b[2*p][1] = r1;
                b[2*p+1][0] = r2; b[2*p+1][1] = r3;
            }
            #pragma unroll
            for (int mi = 0; mi < 4; mi++)
                #pragma unroll
                for (int ni = 0; ni < 8; ni++)
                    mma_bf16(acc[mi][ni], a[mi][0], a[mi][1], a[mi][2], a[mi][3],
                             b[ni][0], b[ni][1]);
        }
        __syncthreads();
    }

    // ---- epilogue ----
    #pragma unroll
    for (int mi = 0; mi < 4; mi++) {
        #pragma unroll
        for (int ni = 0; ni < 8; ni++) {
            const int row0 = rowBase + warpM + mi * 16 + (lane >> 2);
            const int col  = colBase + warpN + ni * 8 + (lane & 3) * 2;
            float v[4];
            #pragma unroll
            for (int r = 0; r < 4; r++) v[r] = acc[mi][ni][r] * scale;
            if (bias) {
                const float b0 = bias[col], b1 = bias[col + 1];
                v[0] += b0; v[1] += b1; v[2] += b0; v[3] += b1;
            }
            if (!OBF16) {
                float* C = (float*)Cout + (long long)z * sC;
                if (residual) {
                    const float* R = residual + (long long)z * sC;
                    float2 r0 = *reinterpret_cast<const float2*>(&R[(long long)row0 * ldc + col]);
                    float2 r1 = *reinterpret_cast<const float2*>(&R[(long long)(row0 + 8) * ldc + col]);
                    v[0] += r0.x; v[1] += r0.y; v[2] += r1.x; v[3] += r1.y;
                }
                *reinterpret_cast<float2*>(&C[(long long)row0 * ldc + col])       = make_float2(v[0], v[1]);
                *reinterpret_cast<float2*>(&C[(long long)(row0 + 8) * ldc + col]) = make_float2(v[2], v[3]);
            } else {
                __nv_bfloat16* C = (__nv_bfloat16*)Cout + (long long)z * sC;
                __nv_bfloat162 p0 = __floats2bfloat162_rn(v[0], v[1]);
                __nv_bfloat162 p1 = __floats2bfloat162_rn(v[2], v[3]);
                *reinterpret_cast<uint32_t*>(&C[(long long)row0 * ldc + col])       = *(uint32_t*)&p0;
                *reinterpret_cast<uint32_t*>(&C[(long long)(row0 + 8) * ldc + col]) = *(uint32_t*)&p1;
            }
        }
    }
}

// ---------------------------------------------------------------------------
// setup: fp32 -> bf16 x, pack biases
// ---------------------------------------------------------------------------
__global__ __launch_bounds__(256)
void conv_bf16(const float* __restrict__ in, __nv_bfloat16* __restrict__ out, long long n)
{
    long long i = ((long long)blockIdx.x * blockDim.x + threadIdx.x) * 4;
    if (i >= n) return;
    float4 f = *reinterpret_cast<const float4*>(in + i);
    __nv_bfloat162 p0 = __floats2bfloat162_rn(f.x, f.y);
    __nv_bfloat162 p1 = __floats2bfloat162_rn(f.z, f.w);
    uint2 o; o.x = *(uint32_t*)&p0; o.y = *(uint32_t*)&p1;
    *reinterpret_cast<uint2*>(out + i) = o;
}

__global__ __launch_bounds__(256)
void pack_bias(const float* __restrict__ bq, const float* __restrict__ bk,
               const float* __restrict__ bv, float* __restrict__ bqkv)
{
    int i = blockIdx.x * blockDim.x + threadIdx.x;
    if (i < U_)              bqkv[i] = bq[i];
    else if (i < 2 * U_)     bqkv[i] = bk[i - U_];
    else if (i < 3 * U_)     bqkv[i] = bv[i - 2 * U_];
}

// all-weights transpose fp32->bf16: z in {0:Wq,1:Wk,2:Wv,3:Wp}
__global__ __launch_bounds__(256)
void wtrans_all(const float* __restrict__ Wq, const float* __restrict__ Wk,
                const float* __restrict__ Wv, const float* __restrict__ Wp,
                __nv_bfloat16* __restrict__ Wqkvt, __nv_bfloat16* __restrict__ Wpt)
{
    __shared__ float tile[32][33];
    const int z = blockIdx.z;
    const float* in = (z == 0) ? Wq : (z == 1) ? Wk : (z == 2) ? Wv : Wp;
    __nv_bfloat16* out = (z < 3) ? (Wqkvt + (size_t)z * U_ * U_) : Wpt;
    const int c0 = blockIdx.x * 32, r0 = blockIdx.y * 32;
    const int x = threadIdx.x, y = threadIdx.y;
    #pragma unroll
    for (int i = 0; i < 32; i += 8)
        tile[y + i][x] = in[(long long)(r0 + y + i) * U_ + c0 + x];
    __syncthreads();
    #pragma unroll
    for (int i = 0; i < 32; i += 8)
        out[(long long)(c0 + y + i) * U_ + r0 + x] = __float2bfloat16(tile[x][y + i]);
}

// V (inside QKV, row stride 1536, col offset 1024) -> VT [U, N] per batch
__global__ __launch_bounds__(256)
void vtrans(const __nv_bfloat16* __restrict__ qkv, __nv_bfloat16* __restrict__ vt)
{
    __shared__ __nv_bfloat16 tile[32][34];
    const int z = blockIdx.z;
    const __nv_bfloat16* in = qkv + (long long)z * N_ * QKVLD + 2 * U_;
    __nv_bfloat16* out = vt + (long long)z * N_ * U_;
    const int c0 = blockIdx.x * 32, r0 = blockIdx.y * 32;
    const int x = threadIdx.x, y = threadIdx.y;
    #pragma unroll
    for (int i = 0; i < 32; i += 8)
        tile[y + i][x] = in[(long long)(r0 + y + i) * QKVLD + c0 + x];
    __syncthreads();
    #pragma unroll
    for (int i = 0; i < 32; i += 8)
        out[(long long)(c0 + y + i) * N_ + r0 + x] = tile[x][y + i];
}

// ---------------------------------------------------------------------------
// row softmax on bf16 [rows x 4096], in place; warp-shuffle reductions
// ---------------------------------------------------------------------------
__global__ __launch_bounds__(256)
void softmax_bf16(__nv_bfloat16* __restrict__ S)
{
    const long long row = blockIdx.x;
    uint4* p = reinterpret_cast<uint4*>(S + row * (long long)N_);
    const int tid = threadIdx.x;
    const int lane = tid & 31, wp = tid >> 5;
    __shared__ float red[8];

    uint4 u[2];
    u[0] = p[tid * 2];
    u[1] = p[tid * 2 + 1];

    float f[16];
    {
        const __nv_bfloat162* h = reinterpret_cast<const __nv_bfloat162*>(u);
        #pragma unroll
        for (int i = 0; i < 8; i++) {
            float2 t = __bfloat1622float2(h[i]);
            f[i * 2] = t.x; f[i * 2 + 1] = t.y;
        }
    }

    float m = f[0];
    #pragma unroll
    for (int i = 1; i < 16; i++) m = fmaxf(m, f[i]);
    #pragma unroll
    for (int o = 16; o > 0; o >>= 1)
        m = fmaxf(m, __shfl_xor_sync(0xFFFFFFFF, m, o));
    if (lane == 0) red[wp] = m;
    __syncthreads();
    {
        float t = red[lane & 7];
        #pragma unroll
        for (int o = 4; o > 0; o >>= 1)
            t = fmaxf(t, __shfl_xor_sync(0xFFFFFFFF, t, o));
        m = t;
    }

    float sum = 0.0f;
    #pragma unroll
    for (int i = 0; i < 16; i++) { f[i] = __expf(f[i] - m); sum += f[i]; }
    #pragma unroll
    for (int o = 16; o > 0; o >>= 1)
        sum += __shfl_xor_sync(0xFFFFFFFF, sum, o);
    __syncthreads();
    if (lane == 0) red[wp] = sum;
    __syncthreads();
    {
        float t = red[lane & 7];
        #pragma unroll
        for (int o = 4; o > 0; o >>= 1)
            t += __shfl_xor_sync(0xFFFFFFFF, t, o);
        sum = t;
    }
    const float inv = 1.0f / sum;

    __nv_bfloat162 h[8];
    #pragma unroll
    for (int i = 0; i < 8; i++)
        h[i] = __floats2bfloat162_rn(f[i * 2] * inv, f[i * 2 + 1] * inv);
    uint4 o[2];
    {
        uint32_t* w = reinterpret_cast<uint32_t*>(o);
        #pragma unroll
        for (int i = 0; i < 8; i++) w[i] = *(uint32_t*)&h[i];
    }
    p[tid * 2]     = o[0];
    p[tid * 2 + 1] = o[1];
}

// ---------------------------------------------------------------------------
extern "C" void kernel_launch(void* const* d_in, const int* in_sizes, int n_in,
                              void* d_out, int out_size)
{
    const float* x  = (const float*)d_in[0];
    const float* Wq = (const float*)d_in[1];
    const float* bq = (const float*)d_in[2];
    const float* Wk = (const float*)d_in[3];
    const float* bk = (const float*)d_in[4];
    const float* Wv = (const float*)d_in[5];
    const float* bv = (const float*)d_in[6];
    const float* Wp = (const float*)d_in[7];
    const float* bp = (const float*)d_in[8];
    float* out = (float*)d_out;

    __nv_bfloat16 *xb, *QKV, *VT, *S, *C, *WQKVT, *WPT;
    float* bqkv;
    cudaGetSymbolAddress((void**)&xb,    g_xb);
    cudaGetSymbolAddress((void**)&QKV,   g_QKV);
    cudaGetSymbolAddress((void**)&VT,    g_VT);
    cudaGetSymbolAddress((void**)&S,     g_S);
    cudaGetSymbolAddress((void**)&C,     g_C);
    cudaGetSymbolAddress((void**)&WQKVT, g_WQKVT);
    cudaGetSymbolAddress((void**)&WPT,   g_WPT);
    cudaGetSymbolAddress((void**)&bqkv,  g_bqkv);

    cudaFuncSetAttribute(gemm_bf16<true>,  cudaFuncAttributeMaxDynamicSharedMemorySize, SM_TOTAL);
    cudaFuncSetAttribute(gemm_bf16<false>, cudaFuncAttributeMaxDynamicSharedMemorySize, SM_TOTAL);

    const float scale = 1.0f / sqrtf((float)U_);

    // 0) setup: x->bf16, transpose weights, pack bias
    conv_bf16<<<(M1 * U_ / 4 + 255) / 256, 256>>>(x, xb, (long long)M1 * U_);
    {
        dim3 tb(32, 8, 1), g(U_ / 32, U_ / 32, 4);
        wtrans_all<<<g, tb>>>(Wq, Wk, Wv, Wp, WQKVT, WPT);
    }
    pack_bias<<<6, 256>>>(bq, bk, bv, bqkv);

    // 1) QKV projection: [16384,1536] = xb @ Wqkv^T + bqkv  -> bf16 interleaved
    {
        dim3 g(QKVLD / BN, M1 / BM, 1);
        gemm_bf16<true><<<g, 128, SM_TOTAL>>>(xb, WQKVT, bqkv, nullptr, QKV,
                                              QKVLD, U_, U_, U_, QKVLD,
                                              0, 0, 0, 1.0f);
    }

    // 2) V^T per batch [512, 4096]
    {
        dim3 tb(32, 8, 1), g(U_ / 32, N_ / 32, B_);
        vtrans<<<g, tb>>>(QKV, VT);
    }

    // 3) S[b] = scale * Q[b] @ K[b]^T -> bf16
    {
        dim3 g(N_ / BN, N_ / BM, B_);
        gemm_bf16<true><<<g, 128, SM_TOTAL>>>(QKV, QKV + U_, nullptr, nullptr, S,
                                              N_, U_, QKVLD, QKVLD, N_,
                                              (long long)N_ * QKVLD, (long long)N_ * QKVLD,
                                              (long long)N_ * N_, scale);
    }

    // 4) softmax rows in place
    softmax_bf16<<<B_ * N_, 256>>>(S);

    // 5) ctx[b] = P[b] @ V[b]   (B operand = V^T rows)
    {
        dim3 g(U_ / BN, N_ / BM, B_);
        gemm_bf16<true><<<g, 128, SM_TOTAL>>>(S, VT, nullptr, nullptr, C,
                                              U_, N_, N_, N_, U_,
                                              (long long)N_ * N_, (long long)U_ * N_,
                                              (long long)N_ * U_, 1.0f);
    }

    // 6) out = x + ctx @ Wp^T + bp  (fp32 out, residual)
    {
        dim3 g(U_ / BN, M1 / BM, 1);
        gemm_bf16<false><<<g, 128, SM_TOTAL>>>(C, WPT, bp, x, out,
                                               U_, U_, U_, U_, U_,
                                               0, 0, 0, 1.0f);
    }
}

// round 13
// speedup vs baseline: 1.0597x; 1.0597x over previous
#include <cuda_runtime.h>
#include <cuda_bf16.h>
#include <math.h>
#include <stdint.h>

// Problem constants
#define B_  4
#define N_  4096
#define U_  512
#define M1  (B_ * N_)
#define QKVLD 1536

// GEMM tiling: CTA 128x128, 8 warps 64x32 (R7 shape), BK=64, 3-stage pipeline
#define BM 128
#define BN 128
#define BK 64
#define SKB 144          // smem row stride bytes (64*2 + 16 pad)
#define NSTAGE 3

static constexpr int ATILE  = BM * SKB;            // 18432 B
static constexpr int STAGEB = 2 * ATILE;           // A+B per stage = 36864 B
static constexpr int SM_TOTAL = NSTAGE * STAGEB;   // 110592 B

// ---------------- scratch (device globals; no allocation allowed) ----------
__device__ __align__(16) __nv_bfloat16 g_xb  [(size_t)M1 * U_];
__device__ __align__(16) __nv_bfloat16 g_QKV [(size_t)M1 * QKVLD];    // Q|K|V per row
__device__ __align__(16) __nv_bfloat16 g_VT  [(size_t)M1 * U_];       // per batch [U, N]
__device__ __align__(16) __nv_bfloat16 g_S   [(size_t)B_ * N_ * N_];  // 128 MB
__device__ __align__(16) __nv_bfloat16 g_C   [(size_t)M1 * U_];       // ctx
__device__ __align__(16) __nv_bfloat16 g_WQKVT[(size_t)3 * U_ * U_];  // [1536,512]
__device__ __align__(16) __nv_bfloat16 g_WPT [(size_t)U_ * U_];
__device__ __align__(16) float         g_bqkv[QKVLD];

// ---------------- PTX helpers ----------------------------------------------
__device__ __forceinline__ uint32_t smem_u32(const void* p) {
    uint32_t a;
    asm("{ .reg .u64 t; cvta.to.shared.u64 t, %1; cvt.u32.u64 %0, t; }" : "=r"(a) : "l"(p));
    return a;
}
#define CP_ASYNC16(dst, src) \
    asm volatile("cp.async.cg.shared.global [%0], [%1], 16;\n" :: "r"(dst), "l"(src))
#define CP_COMMIT() asm volatile("cp.async.commit_group;\n" ::: "memory")
#define CP_WAIT(n)  asm volatile("cp.async.wait_group %0;\n" :: "n"(n) : "memory")

__device__ __forceinline__ void ldsm_x4(uint32_t& r0, uint32_t& r1, uint32_t& r2,
                                        uint32_t& r3, uint32_t addr) {
    asm volatile("ldmatrix.sync.aligned.m8n8.x4.shared.b16 {%0,%1,%2,%3}, [%4];"
                 : "=r"(r0), "=r"(r1), "=r"(r2), "=r"(r3) : "r"(addr));
}
__device__ __forceinline__ void mma_bf16(float c[4],
                                         uint32_t a0, uint32_t a1, uint32_t a2, uint32_t a3,
                                         uint32_t b0, uint32_t b1) {
    asm volatile(
        "mma.sync.aligned.m16n8k16.row.col.f32.bf16.bf16.f32 "
        "{%0,%1,%2,%3}, {%4,%5,%6,%7}, {%8,%9}, {%0,%1,%2,%3};\n"
        : "+f"(c[0]), "+f"(c[1]), "+f"(c[2]), "+f"(c[3])
        : "r"(a0), "r"(a1), "r"(a2), "r"(a3), "r"(b0), "r"(b1));
}

// ---------------------------------------------------------------------------
// bf16 NT GEMM:  C[z] = scale * A[z] @ B[z]^T (+bias) (+residual)
// A: [M,K] lda-strided. B: [N,K] ldb-strided. M,N % 128 == 0, K % 64 == 0.
// 256 threads, 8 warps 64x32. 3-stage cp.async pipeline, 1 barrier/ktile.
// ---------------------------------------------------------------------------
template <bool OBF16>
__global__ __launch_bounds__(256, 2)
void gemm_bf16(const __nv_bfloat16* __restrict__ A,
               const __nv_bfloat16* __restrict__ Bm,
               const float* __restrict__ bias,
               const float* __restrict__ residual,
               void* __restrict__ Cout,
               int N, int K, int lda, int ldb, int ldc,
               long long sA, long long sB, long long sC,
               float scale)
{
    extern __shared__ char smem[];
    const uint32_t sbase = smem_u32(smem);
    const int tid  = threadIdx.x;
    const int wid  = tid >> 5;
    const int lane = tid & 31;

    const int z = blockIdx.z;
    A  += (long long)z * sA;
    Bm += (long long)z * sB;

    const int rowBase = blockIdx.y * BM;
    const int colBase = blockIdx.x * BN;
    const int warpM = (wid & 1) * 64;
    const int warpN = (wid >> 1) * 32;

    const __nv_bfloat16* Aptr = A + (long long)rowBase * lda;
    const __nv_bfloat16* Bptr = Bm + (long long)colBase * ldb;

    float acc[4][4][4];
    #pragma unroll
    for (int mi = 0; mi < 4; mi++)
        #pragma unroll
        for (int ni = 0; ni < 4; ni++)
            #pragma unroll
            for (int r = 0; r < 4; r++)
                acc[mi][ni][r] = 0.0f;

    const int lr = tid >> 3;
    const int lc = tid & 7;
    auto load_tile = [&](int s, int k0) {
        const uint32_t abase = sbase + s * STAGEB;
        const uint32_t bbase = abase + ATILE;
        #pragma unroll
        for (int i = 0; i < 4; i++) {
            const int r = lr + i * 32;
            CP_ASYNC16(abase + r * SKB + lc * 16,
                       Aptr + (long long)r * lda + k0 + lc * 8);
        }
        #pragma unroll
        for (int i = 0; i < 4; i++) {
            const int r = lr + i * 32;
            CP_ASYNC16(bbase + r * SKB + lc * 16,
                       Bptr + (long long)r * ldb + k0 + lc * 8);
        }
        CP_COMMIT();
    };

    const int lm = lane & 7;
    const int lt = lane >> 3;
    const int aRowOff = lm + (lt & 1) * 8;
    const int aKOff   = (lt >> 1) * 8;
    const int bRowOff = lm + (lt >> 1) * 8;
    const int bKOff   = (lt & 1) * 8;

    const int T = K / BK;
    load_tile(0, 0);
    if (T > 1) load_tile(1, BK);

    int sIdx = 0;
    for (int t = 0; t < T; t++) {
        if (t + 1 < T) { CP_WAIT(1); } else { CP_WAIT(0); }
        __syncthreads();
        // issue load for t+2 into the buffer consumed at iteration t-1
        if (t + 2 < T) {
            int s2 = sIdx + 2; if (s2 >= NSTAGE) s2 -= NSTAGE;
            load_tile(s2, (t + 2) * BK);
        }

        const uint32_t Asb = sbase + sIdx * STAGEB;
        const uint32_t Bsb = Asb + ATILE;

        #pragma unroll
        for (int kk = 0; kk < 4; kk++) {
            uint32_t a[4][4], b[4][2];
            #pragma unroll
            for (int mi = 0; mi < 4; mi++) {
                uint32_t addr = Asb + (warpM + mi * 16 + aRowOff) * SKB
                              + (kk * 16 + aKOff) * 2;
                ldsm_x4(a[mi][0], a[mi][1], a[mi][2], a[mi][3], addr);
            }
            #pragma unroll
            for (int p = 0; p < 2; p++) {
                uint32_t addr = Bsb + (warpN + p * 16 + bRowOff) * SKB
                              + (kk * 16 + bKOff) * 2;
                uint32_t r0, r1, r2, r3;
                ldsm_x4(r0, r1, r2, r3, addr);
                b[2*p][0] = r0;   b[2*p][1] = r1;
                b[2*p+1][0] = r2; b[2*p+1][1] = r3;
            }
            #pragma unroll
            for (int mi = 0; mi < 4; mi++)
                #pragma unroll
                for (int ni = 0; ni < 4; ni++)
                    mma_bf16(acc[mi][ni], a[mi][0], a[mi][1], a[mi][2], a[mi][3],
                             b[ni][0], b[ni][1]);
        }
        sIdx++; if (sIdx >= NSTAGE) sIdx = 0;
    }

    // ---- epilogue ----
    #pragma unroll
    for (int mi = 0; mi < 4; mi++) {
        #pragma unroll
        for (int ni = 0; ni < 4; ni++) {
            const int row0 = rowBase + warpM + mi * 16 + (lane >> 2);
            const int col  = colBase + warpN + ni * 8 + (lane & 3) * 2;
            float v[4];
            #pragma unroll
            for (int r = 0; r < 4; r++) v[r] = acc[mi][ni][r] * scale;
            if (bias) {
                const float b0 = bias[col], b1 = bias[col + 1];
                v[0] += b0; v[1] += b1; v[2] += b0; v[3] += b1;
            }
            if (!OBF16) {
                float* C = (float*)Cout + (long long)z * sC;
                if (residual) {
                    const float* R = residual + (long long)z * sC;
                    float2 r0 = *reinterpret_cast<const float2*>(&R[(long long)row0 * ldc + col]);
                    float2 r1 = *reinterpret_cast<const float2*>(&R[(long long)(row0 + 8) * ldc + col]);
                    v[0] += r0.x; v[1] += r0.y; v[2] += r1.x; v[3] += r1.y;
                }
                *reinterpret_cast<float2*>(&C[(long long)row0 * ldc + col])       = make_float2(v[0], v[1]);
                *reinterpret_cast<float2*>(&C[(long long)(row0 + 8) * ldc + col]) = make_float2(v[2], v[3]);
            } else {
                __nv_bfloat16* C = (__nv_bfloat16*)Cout + (long long)z * sC;
                __nv_bfloat162 p0 = __floats2bfloat162_rn(v[0], v[1]);
                __nv_bfloat162 p1 = __floats2bfloat162_rn(v[2], v[3]);
                *reinterpret_cast<uint32_t*>(&C[(long long)row0 * ldc + col])       = *(uint32_t*)&p0;
                *reinterpret_cast<uint32_t*>(&C[(long long)(row0 + 8) * ldc + col]) = *(uint32_t*)&p1;
            }
        }
    }
}

// ---------------------------------------------------------------------------
// setup: fp32 -> bf16 x, pack biases
// ---------------------------------------------------------------------------
__global__ __launch_bounds__(256)
void conv_bf16(const float* __restrict__ in, __nv_bfloat16* __restrict__ out, long long n)
{
    long long i = ((long long)blockIdx.x * blockDim.x + threadIdx.x) * 4;
    if (i >= n) return;
    float4 f = *reinterpret_cast<const float4*>(in + i);
    __nv_bfloat162 p0 = __floats2bfloat162_rn(f.x, f.y);
    __nv_bfloat162 p1 = __floats2bfloat162_rn(f.z, f.w);
    uint2 o; o.x = *(uint32_t*)&p0; o.y = *(uint32_t*)&p1;
    *reinterpret_cast<uint2*>(out + i) = o;
}

__global__ __launch_bounds__(256)
void pack_bias(const float* __restrict__ bq, const float* __restrict__ bk,
               const float* __restrict__ bv, float* __restrict__ bqkv)
{
    int i = blockIdx.x * blockDim.x + threadIdx.x;
    if (i < U_)              bqkv[i] = bq[i];
    else if (i < 2 * U_)     bqkv[i] = bk[i - U_];
    else if (i < 3 * U_)     bqkv[i] = bv[i - 2 * U_];
}

// all-weights transpose fp32->bf16: z in {0:Wq,1:Wk,2:Wv,3:Wp}
__global__ __launch_bounds__(256)
void wtrans_all(const float* __restrict__ Wq, const float* __restrict__ Wk,
                const float* __restrict__ Wv, const float* __restrict__ Wp,
                __nv_bfloat16* __restrict__ Wqkvt, __nv_bfloat16* __restrict__ Wpt)
{
    __shared__ float tile[32][33];
    const int z = blockIdx.z;
    const float* in = (z == 0) ? Wq : (z == 1) ? Wk : (z == 2) ? Wv : Wp;
    __nv_bfloat16* out = (z < 3) ? (Wqkvt + (size_t)z * U_ * U_) : Wpt;
    const int c0 = blockIdx.x * 32, r0 = blockIdx.y * 32;
    const int x = threadIdx.x, y = threadIdx.y;
    #pragma unroll
    for (int i = 0; i < 32; i += 8)
        tile[y + i][x] = in[(long long)(r0 + y + i) * U_ + c0 + x];
    __syncthreads();
    #pragma unroll
    for (int i = 0; i < 32; i += 8)
        out[(long long)(c0 + y + i) * U_ + r0 + x] = __float2bfloat16(tile[x][y + i]);
}

// V (inside QKV, row stride 1536, col offset 1024) -> VT [U, N] per batch
__global__ __launch_bounds__(256)
void vtrans(const __nv_bfloat16* __restrict__ qkv, __nv_bfloat16* __restrict__ vt)
{
    __shared__ __nv_bfloat16 tile[32][34];
    const int z = blockIdx.z;
    const __nv_bfloat16* in = qkv + (long long)z * N_ * QKVLD + 2 * U_;
    __nv_bfloat16* out = vt + (long long)z * N_ * U_;
    const int c0 = blockIdx.x * 32, r0 = blockIdx.y * 32;
    const int x = threadIdx.x, y = threadIdx.y;
    #pragma unroll
    for (int i = 0; i < 32; i += 8)
        tile[y + i][x] = in[(long long)(r0 + y + i) * QKVLD + c0 + x];
    __syncthreads();
    #pragma unroll
    for (int i = 0; i < 32; i += 8)
        out[(long long)(c0 + y + i) * N_ + r0 + x] = tile[x][y + i];
}

// ---------------------------------------------------------------------------
// row softmax on bf16 [rows x 4096], in place; warp-shuffle reductions
// ---------------------------------------------------------------------------
__global__ __launch_bounds__(256)
void softmax_bf16(__nv_bfloat16* __restrict__ S)
{
    const long long row = blockIdx.x;
    uint4* p = reinterpret_cast<uint4*>(S + row * (long long)N_);
    const int tid = threadIdx.x;
    const int lane = tid & 31, wp = tid >> 5;
    __shared__ float red[8];

    uint4 u[2];
    u[0] = p[tid * 2];
    u[1] = p[tid * 2 + 1];

    float f[16];
    {
        const __nv_bfloat162* h = reinterpret_cast<const __nv_bfloat162*>(u);
        #pragma unroll
        for (int i = 0; i < 8; i++) {
            float2 t = __bfloat1622float2(h[i]);
            f[i * 2] = t.x; f[i * 2 + 1] = t.y;
        }
    }

    float m = f[0];
    #pragma unroll
    for (int i = 1; i < 16; i++) m = fmaxf(m, f[i]);
    #pragma unroll
    for (int o = 16; o > 0; o >>= 1)
        m = fmaxf(m, __shfl_xor_sync(0xFFFFFFFF, m, o));
    if (lane == 0) red[wp] = m;
    __syncthreads();
    {
        float t = red[lane & 7];
        #pragma unroll
        for (int o = 4; o > 0; o >>= 1)
            t = fmaxf(t, __shfl_xor_sync(0xFFFFFFFF, t, o));
        m = t;
    }

    float sum = 0.0f;
    #pragma unroll
    for (int i = 0; i < 16; i++) { f[i] = __expf(f[i] - m); sum += f[i]; }
    #pragma unroll
    for (int o = 16; o > 0; o >>= 1)
        sum += __shfl_xor_sync(0xFFFFFFFF, sum, o);
    __syncthreads();
    if (lane == 0) red[wp] = sum;
    __syncthreads();
    {
        float t = red[lane & 7];
        #pragma unroll
        for (int o = 4; o > 0; o >>= 1)
            t += __shfl_xor_sync(0xFFFFFFFF, t, o);
        sum = t;
    }
    const float inv = 1.0f / sum;

    __nv_bfloat162 h[8];
    #pragma unroll
    for (int i = 0; i < 8; i++)
        h[i] = __floats2bfloat162_rn(f[i * 2] * inv, f[i * 2 + 1] * inv);
    uint4 o[2];
    {
        uint32_t* w = reinterpret_cast<uint32_t*>(o);
        #pragma unroll
        for (int i = 0; i < 8; i++) w[i] = *(uint32_t*)&h[i];
    }
    p[tid * 2]     = o[0];
    p[tid * 2 + 1] = o[1];
}

// ---------------------------------------------------------------------------
extern "C" void kernel_launch(void* const* d_in, const int* in_sizes, int n_in,
                              void* d_out, int out_size)
{
    const float* x  = (const float*)d_in[0];
    const float* Wq = (const float*)d_in[1];
    const float* bq = (const float*)d_in[2];
    const float* Wk = (const float*)d_in[3];
    const float* bk = (const float*)d_in[4];
    const float* Wv = (const float*)d_in[5];
    const float* bv = (const float*)d_in[6];
    const float* Wp = (const float*)d_in[7];
    const float* bp = (const float*)d_in[8];
    float* out = (float*)d_out;

    __nv_bfloat16 *xb, *QKV, *VT, *S, *C, *WQKVT, *WPT;
    float* bqkv;
    cudaGetSymbolAddress((void**)&xb,    g_xb);
    cudaGetSymbolAddress((void**)&QKV,   g_QKV);
    cudaGetSymbolAddress((void**)&VT,    g_VT);
    cudaGetSymbolAddress((void**)&S,     g_S);
    cudaGetSymbolAddress((void**)&C,     g_C);
    cudaGetSymbolAddress((void**)&WQKVT, g_WQKVT);
    cudaGetSymbolAddress((void**)&WPT,   g_WPT);
    cudaGetSymbolAddress((void**)&bqkv,  g_bqkv);

    cudaFuncSetAttribute(gemm_bf16<true>,  cudaFuncAttributeMaxDynamicSharedMemorySize, SM_TOTAL);
    cudaFuncSetAttribute(gemm_bf16<false>, cudaFuncAttributeMaxDynamicSharedMemorySize, SM_TOTAL);

    const float scale = 1.0f / sqrtf((float)U_);

    // 0) setup: x->bf16, transpose weights, pack bias
    conv_bf16<<<(M1 * U_ / 4 + 255) / 256, 256>>>(x, xb, (long long)M1 * U_);
    {
        dim3 tb(32, 8, 1), g(U_ / 32, U_ / 32, 4);
        wtrans_all<<<g, tb>>>(Wq, Wk, Wv, Wp, WQKVT, WPT);
    }
    pack_bias<<<6, 256>>>(bq, bk, bv, bqkv);

    // 1) QKV projection: [16384,1536] = xb @ Wqkv^T + bqkv  -> bf16 interleaved
    {
        dim3 g(QKVLD / BN, M1 / BM, 1);
        gemm_bf16<true><<<g, 256, SM_TOTAL>>>(xb, WQKVT, bqkv, nullptr, QKV,
                                              QKVLD, U_, U_, U_, QKVLD,
                                              0, 0, 0, 1.0f);
    }

    // 2) V^T per batch [512, 4096]
    {
        dim3 tb(32, 8, 1), g(U_ / 32, N_ / 32, B_);
        vtrans<<<g, tb>>>(QKV, VT);
    }

    // 3) S[b] = scale * Q[b] @ K[b]^T -> bf16
    {
        dim3 g(N_ / BN, N_ / BM, B_);
        gemm_bf16<true><<<g, 256, SM_TOTAL>>>(QKV, QKV + U_, nullptr, nullptr, S,
                                              N_, U_, QKVLD, QKVLD, N_,
                                              (long long)N_ * QKVLD, (long long)N_ * QKVLD,
                                              (long long)N_ * N_, scale);
    }

    // 4) softmax rows in place
    softmax_bf16<<<B_ * N_, 256>>>(S);

    // 5) ctx[b] = P[b] @ V[b]   (B operand = V^T rows)
    {
        dim3 g(U_ / BN, N_ / BM, B_);
        gemm_bf16<true><<<g, 256, SM_TOTAL>>>(S, VT, nullptr, nullptr, C,
                                              U_, N_, N_, N_, U_,
                                              (long long)N_ * N_, (long long)U_ * N_,
                                              (long long)N_ * U_, 1.0f);
    }

    // 6) out = x + ctx @ Wp^T + bp  (fp32 out, residual)
    {
        dim3 g(U_ / BN, M1 / BM, 1);
        gemm_bf16<false><<<g, 256, SM_TOTAL>>>(C, WPT, bp, x, out,
                                               U_, U_, U_, U_, U_,
                                               0, 0, 0, 1.0f);
    }
}